// round 5
// baseline (speedup 1.0000x reference)
#include <cuda_runtime.h>
#include <cuda_bf16.h>
#include <cuda_fp16.h>
#include <cstdint>
#include <math.h>

#define N_INST 256
#define BATCH  128
#define IN_DIM 1024
#define L_DIM  512

// ---------------- device scratch (allocation-free rule) ----------------
__device__ __align__(256) __nv_bfloat16 g_xh[(size_t)N_INST * BATCH * IN_DIM]; // 64MB
__device__ __align__(256) __nv_bfloat16 g_xl[(size_t)N_INST * BATCH * IN_DIM]; // 64MB
__device__ __align__(256) __nv_bfloat16 g_vh[L_DIM * IN_DIM]; // [l][k] transposed
__device__ __align__(256) __nv_bfloat16 g_vl[L_DIM * IN_DIM];
__device__ __align__(256) __nv_bfloat16 g_uh[L_DIM * IN_DIM];
__device__ __align__(256) __nv_bfloat16 g_ul[L_DIM * IN_DIM];
__device__ float g_part[1024 * BATCH];   // partial scores per (instance, l-chunk)

// ---------------- helpers ----------------
__device__ __forceinline__ uint32_t smem_u32(const void* p) {
    uint32_t a;
    asm("{ .reg .u64 t; cvta.to.shared.u64 t, %1; cvt.u32.u64 %0, t; }" : "=r"(a) : "l"(p));
    return a;
}
// 64B-row swizzle: XOR row bits [8:7] into 16B-chunk bits [5:4]
#define SWZ64(off) ((off) ^ (((off) >> 3) & 0x30))

#define CP16(dst, src) \
    asm volatile("cp.async.cg.shared.global [%0], [%1], 16;" :: "r"(dst), "l"(src))
#define CP_COMMIT() asm volatile("cp.async.commit_group;" ::: "memory")
#define CP_WAIT(n)  asm volatile("cp.async.wait_group %0;" :: "n"(n) : "memory")

__device__ __forceinline__ void ldsm4(uint32_t* r, uint32_t addr) {
    asm volatile("ldmatrix.sync.aligned.m8n8.x4.shared.b16 {%0,%1,%2,%3}, [%4];"
                 : "=r"(r[0]), "=r"(r[1]), "=r"(r[2]), "=r"(r[3]) : "r"(addr));
}
__device__ __forceinline__ void mma16816(float* c, const uint32_t* a, const uint32_t* b) {
    asm volatile("mma.sync.aligned.m16n8k16.row.col.f32.bf16.bf16.f32 "
                 "{%0,%1,%2,%3}, {%4,%5,%6,%7}, {%8,%9}, {%0,%1,%2,%3};"
                 : "+f"(c[0]), "+f"(c[1]), "+f"(c[2]), "+f"(c[3])
                 : "r"(a[0]), "r"(a[1]), "r"(a[2]), "r"(a[3]), "r"(b[0]), "r"(b[1]));
}
__device__ __forceinline__ float fast_tanh(float x) {
    float t = __expf(2.0f * x);
    return (t - 1.0f) / (t + 1.0f);
}
__device__ __forceinline__ float fast_sigmoid(float x) {
    return 1.0f / (1.0f + __expf(-x));
}

// ---------------- prep kernels ----------------
__global__ void prep_x_kernel(const float4* __restrict__ x4) {
    size_t i = (size_t)blockIdx.x * 256 + threadIdx.x;      // 8388608 threads
    float4 f = x4[i];
    float a[4] = {f.x, f.y, f.z, f.w};
    unsigned short hs[4], ls[4];
#pragma unroll
    for (int j = 0; j < 4; j++) {
        __nv_bfloat16 h = __float2bfloat16(a[j]);
        float hf = __bfloat162float(h);
        __nv_bfloat16 lo = __float2bfloat16(a[j] - hf);
        hs[j] = __bfloat16_as_ushort(h);
        ls[j] = __bfloat16_as_ushort(lo);
    }
    uint2 hh = make_uint2((uint32_t)hs[0] | ((uint32_t)hs[1] << 16),
                          (uint32_t)hs[2] | ((uint32_t)hs[3] << 16));
    uint2 ll = make_uint2((uint32_t)ls[0] | ((uint32_t)ls[1] << 16),
                          (uint32_t)ls[2] | ((uint32_t)ls[3] << 16));
    size_t o = i * 4;
    *(uint2*)(g_xh + o) = hh;
    *(uint2*)(g_xl + o) = ll;
}

__global__ void prep_vu_kernel(const float* __restrict__ v, const float* __restrict__ u) {
    int gid = blockIdx.x * 256 + threadIdx.x;               // 524288 threads
    int k = gid & (IN_DIM - 1);
    int l = gid >> 10;
    float fv = v[(size_t)k * L_DIM + l];
    float fu = u[(size_t)k * L_DIM + l];
    __nv_bfloat16 vh = __float2bfloat16(fv);
    __nv_bfloat16 vl = __float2bfloat16(fv - __bfloat162float(vh));
    __nv_bfloat16 uh = __float2bfloat16(fu);
    __nv_bfloat16 ul = __float2bfloat16(fu - __bfloat162float(uh));
    size_t o = (size_t)l * IN_DIM + k;
    g_vh[o] = vh; g_vl[o] = vl; g_uh[o] = uh; g_ul[o] = ul;
}

// ---------------- main fused GEMM kernel ----------------
// One CTA per (instance n, l-chunk lc). 256 threads / 8 warps.
// Warp tile: 64 M x 64 N. nw = wid>>1 in 0..3 (<2: V cols, >=2: U cols),
// mw = wid&1 (rows mw*64..+63).
// SMEM map (bytes):
#define SM_W      0          // 128 f32 = 512
#define SM_RED    512        // 256 f32 = 1024
#define SM_STASH  1536       // 128 rows x 264B (fp16, padded) -> ends 35328
#define STASH_STRIDE 264
#define SM_TILES  35328      // 3 stages x 48KB
#define BUF_STRIDE 49152     // per stage: A_hi 8K, A_lo 8K, B_hi 16K, B_lo 16K
#define OFF_A_HI  0
#define OFF_A_LO  8192
#define OFF_B_HI  16384
#define OFF_B_LO  32768
#define SM_TOTAL  (SM_TILES + 3 * BUF_STRIDE)   // 182784

#define BK 32
#define NI (IN_DIM / BK)     // 32 K-iterations

__global__ void __launch_bounds__(256, 1)
mil_gemm_kernel(const float* __restrict__ w)
{
    extern __shared__ char smem[];
    const int task = blockIdx.x;       // 0..1023
    const int n    = task >> 2;
    const int lc   = task & 3;
    const int l0   = lc * 128;
    const int tid  = threadIdx.x;
    const int lane = tid & 31;
    const int wid  = tid >> 5;
    const int mw   = wid & 1;    // M band: rows mw*64..+63
    const int nw   = wid >> 1;   // N band: combined cols nw*64..+63 (nw<2: V, nw>=2: U)
    const uint32_t smem_base = smem_u32(smem);

    // w slice for this l-chunk into smem
    float* ws = (float*)(smem + SM_W);
    if (tid < 128) ws[tid] = w[l0 + tid];

    const __nv_bfloat16* xh = g_xh + (size_t)n * BATCH * IN_DIM;
    const __nv_bfloat16* xl = g_xl + (size_t)n * BATCH * IN_DIM;
    const size_t lofs = (size_t)l0 * IN_DIM;

    // ---- per-thread cp.async assignments ----
    // A: thread handles one full 64B row-stripe of xh or xl.
    const int hiloA = tid >> 7;          // 0: hi, 1: lo
    const int arow  = tid & 127;
    const __nv_bfloat16* srcA = (hiloA ? xl : xh) + (size_t)arow * IN_DIM;
    uint32_t dstA[4];
#pragma unroll
    for (int j = 0; j < 4; j++)
        dstA[j] = SM_TILES + (hiloA ? OFF_A_LO : OFF_A_HI) + SWZ64(arow * 64 + j * 16);

    // B: thread handles two 64B row-stripes (brow0, brow0+1) of V/U hi or lo.
    const int hiloB = tid >> 7;
    const int brow0 = (tid & 127) * 2;
    const __nv_bfloat16* srcB[2];
    uint32_t dstB[2][4];
#pragma unroll
    for (int r = 0; r < 2; r++) {
        int brow = brow0 + r;
        const __nv_bfloat16* mat;
        if (brow < 128) mat = hiloB ? g_vl : g_vh;
        else            mat = hiloB ? g_ul : g_uh;
        srcB[r] = mat + lofs + (size_t)(brow & 127) * IN_DIM;
#pragma unroll
        for (int j = 0; j < 4; j++)
            dstB[r][j] = SM_TILES + (hiloB ? OFF_B_LO : OFF_B_HI) + SWZ64(brow * 64 + j * 16);
    }

    float acc[4][8][4];
#pragma unroll
    for (int mt = 0; mt < 4; mt++)
#pragma unroll
        for (int nt = 0; nt < 8; nt++)
#pragma unroll
            for (int r = 0; r < 4; r++) acc[mt][nt][r] = 0.f;

    // ---- prologue: stages 0 and 1 ----
#pragma unroll
    for (int s = 0; s < 2; s++) {
        uint32_t bb = smem_base + s * BUF_STRIDE;
        int k0 = s * BK;
#pragma unroll
        for (int j = 0; j < 4; j++) CP16(bb + dstA[j], srcA + k0 + j * 8);
#pragma unroll
        for (int r = 0; r < 2; r++)
#pragma unroll
            for (int j = 0; j < 4; j++) CP16(bb + dstB[r][j], srcB[r] + k0 + j * 8);
        CP_COMMIT();
    }

    int slot = 0, nslot = 2;
    for (int it = 0; it < NI; it++) {
        if (it + 1 < NI) { CP_WAIT(1); } else { CP_WAIT(0); }
        __syncthreads();
        if (it + 2 < NI) {
            uint32_t bb = smem_base + nslot * BUF_STRIDE;
            int k0 = (it + 2) * BK;
#pragma unroll
            for (int j = 0; j < 4; j++) CP16(bb + dstA[j], srcA + k0 + j * 8);
#pragma unroll
            for (int r = 0; r < 2; r++)
#pragma unroll
                for (int j = 0; j < 4; j++) CP16(bb + dstB[r][j], srcB[r] + k0 + j * 8);
            CP_COMMIT();
            nslot = (nslot == 2) ? 0 : nslot + 1;
        }

        const uint32_t bb = smem_base + slot * BUF_STRIDE;
        slot = (slot == 2) ? 0 : slot + 1;
        const uint32_t aHi = bb + SM_TILES + OFF_A_HI;
        const uint32_t aLo = bb + SM_TILES + OFF_A_LO;
        const uint32_t bHi = bb + SM_TILES + OFF_B_HI;
        const uint32_t bLo = bb + SM_TILES + OFF_B_LO;

#pragma unroll
        for (int ks = 0; ks < 2; ks++) {
            // A fragments: row = mw*64 + mt*16 + (lane&15), k-half = (lane>>4)*8
            uint32_t ah[4][4], al[4][4];
            const uint32_t akoff = ks * 32 + (lane >> 4) * 16;
#pragma unroll
            for (int mt = 0; mt < 4; mt++) {
                uint32_t rowb = (mw * 64 + mt * 16 + (lane & 15)) * 64;
                uint32_t so = SWZ64(rowb + akoff);
                ldsm4(ah[mt], aHi + so);
                ldsm4(al[mt], aLo + so);
            }
            const uint32_t bkoff = ks * 32 + ((lane >> 3) & 1) * 16;
#pragma unroll
            for (int ntp = 0; ntp < 4; ntp++) {
                uint32_t rowb = (nw * 64 + ntp * 16 + ((lane >> 4) & 1) * 8 + (lane & 7)) * 64;
                uint32_t so = SWZ64(rowb + bkoff);
                uint32_t bh[4], bl[4];
                ldsm4(bh, bHi + so);
                ldsm4(bl, bLo + so);
#pragma unroll
                for (int half = 0; half < 2; half++) {
                    int nt = ntp * 2 + half;
                    // term-major order: same acc revisited only every 4 MMAs
#pragma unroll
                    for (int mt = 0; mt < 4; mt++)
                        mma16816(acc[mt][nt], ah[mt], bh + half * 2);
#pragma unroll
                    for (int mt = 0; mt < 4; mt++)
                        mma16816(acc[mt][nt], ah[mt], bl + half * 2);
#pragma unroll
                    for (int mt = 0; mt < 4; mt++)
                        mma16816(acc[mt][nt], al[mt], bh + half * 2);
                }
            }
        }
    }
    __syncthreads();

    // ---- epilogue ----
    if (nw < 2) {
        // V warps: stash tanh as fp16
#pragma unroll
        for (int mt = 0; mt < 4; mt++)
#pragma unroll
            for (int nt = 0; nt < 8; nt++) {
                int col = nw * 64 + nt * 8 + (lane & 3) * 2;
#pragma unroll
                for (int half = 0; half < 2; half++) {
                    int row = mw * 64 + mt * 16 + half * 8 + (lane >> 2);
                    float h0 = fast_tanh(acc[mt][nt][half * 2 + 0]);
                    float h1 = fast_tanh(acc[mt][nt][half * 2 + 1]);
                    *(__half2*)(smem + SM_STASH + row * STASH_STRIDE + col * 2) =
                        __floats2half2_rn(h0, h1);
                }
            }
    }
    __syncthreads();

    float rowacc[8] = {0.f, 0.f, 0.f, 0.f, 0.f, 0.f, 0.f, 0.f};
    if (nw >= 2) {
        // U warps: gate + weight
#pragma unroll
        for (int mt = 0; mt < 4; mt++)
#pragma unroll
            for (int nt = 0; nt < 8; nt++) {
                int vcol = (nw - 2) * 64 + nt * 8 + (lane & 3) * 2;
                float w0 = ws[vcol + 0];
                float w1 = ws[vcol + 1];
#pragma unroll
                for (int half = 0; half < 2; half++) {
                    int row = mw * 64 + mt * 16 + half * 8 + (lane >> 2);
                    __half2 hh = *(const __half2*)(smem + SM_STASH +
                                                   row * STASH_STRIDE + vcol * 2);
                    float g0 = fast_sigmoid(acc[mt][nt][half * 2 + 0]);
                    float g1 = fast_sigmoid(acc[mt][nt][half * 2 + 1]);
                    rowacc[mt * 2 + half] += __low2float(hh)  * g0 * w0 +
                                             __high2float(hh) * g1 * w1;
                }
            }
    }
    __syncthreads();

    // ---- final reduction: 4 U warps -> 128 partial scores (2 col-copies) ----
    float* red = (float*)(smem + SM_RED);
    if (nw >= 2) {
#pragma unroll
        for (int ri = 0; ri < 8; ri++) {
            float p = rowacc[ri];
            p += __shfl_xor_sync(0xffffffffu, p, 1);
            p += __shfl_xor_sync(0xffffffffu, p, 2);
            if ((lane & 3) == 0) {
                int mt = ri >> 1, half = ri & 1;
                int row = mw * 64 + mt * 16 + half * 8 + (lane >> 2);
                red[(nw - 2) * 128 + row] = p;
            }
        }
    }
    __syncthreads();
    if (tid < BATCH)
        g_part[(size_t)task * BATCH + tid] = red[tid] + red[128 + tid];
}

// ---------------- softmax over instance axis (sums 4 l-chunk partials) ----------------
__global__ void softmax_kernel(float* __restrict__ out)
{
    const int b   = blockIdx.x;    // 0..127
    const int tid = threadIdx.x;   // 0..255 == n
    __shared__ float sh[256];

    const float* p = g_part + ((size_t)tid * 4) * BATCH + b;
    float s = p[0] + p[BATCH] + p[2 * BATCH] + p[3 * BATCH];
    sh[tid] = s;
    __syncthreads();
#pragma unroll
    for (int off = 128; off > 0; off >>= 1) {
        if (tid < off) sh[tid] = fmaxf(sh[tid], sh[tid + off]);
        __syncthreads();
    }
    float m = sh[0];
    __syncthreads();
    float e = __expf(s - m);
    sh[tid] = e;
    __syncthreads();
#pragma unroll
    for (int off = 128; off > 0; off >>= 1) {
        if (tid < off) sh[tid] += sh[tid + off];
        __syncthreads();
    }
    out[(size_t)tid * BATCH + b] = e / sh[0];
}

extern "C" void kernel_launch(void* const* d_in, const int* in_sizes, int n_in,
                              void* d_out, int out_size)
{
    const float* x = (const float*)d_in[0];
    const float* v = (const float*)d_in[1];
    const float* u = (const float*)d_in[2];
    const float* w = (const float*)d_in[3];
    float* out = (float*)d_out;

    cudaFuncSetAttribute(mil_gemm_kernel,
                         cudaFuncAttributeMaxDynamicSharedMemorySize, SM_TOTAL);

    prep_x_kernel<<<32768, 256>>>((const float4*)x);
    prep_vu_kernel<<<2048, 256>>>(v, u);
    mil_gemm_kernel<<<1024, 256, SM_TOTAL>>>(w);
    softmax_kernel<<<BATCH, 256>>>(out);
}

// round 6
// speedup vs baseline: 2.0202x; 2.0202x over previous
#include <cuda_runtime.h>
#include <cuda_fp16.h>
#include <cstdint>
#include <math.h>

#define N_INST 256
#define BATCH  128
#define IN_DIM 1024
#define L_DIM  512

// ---------------- device scratch (allocation-free rule) ----------------
__device__ __align__(256) __half g_xh[(size_t)N_INST * BATCH * IN_DIM]; // 64MB (fp16 hi)
__device__ __align__(256) __half g_xl[(size_t)N_INST * BATCH * IN_DIM]; // 64MB (fp16 lo)
__device__ __align__(256) __half g_v[L_DIM * IN_DIM];  // [l][k] transposed, fp16
__device__ __align__(256) __half g_u[L_DIM * IN_DIM];
__device__ float g_part[1024 * BATCH];   // partial scores per (instance, l-chunk)

// ---------------- helpers ----------------
__device__ __forceinline__ uint32_t smem_u32(const void* p) {
    uint32_t a;
    asm("{ .reg .u64 t; cvta.to.shared.u64 t, %1; cvt.u32.u64 %0, t; }" : "=r"(a) : "l"(p));
    return a;
}
// 64B-row swizzle: XOR row bits [8:7] into 16B-chunk bits [5:4]
#define SWZ64(off) ((off) ^ (((off) >> 3) & 0x30))

#define CP16(dst, src) \
    asm volatile("cp.async.cg.shared.global [%0], [%1], 16;" :: "r"(dst), "l"(src))
#define CP_COMMIT() asm volatile("cp.async.commit_group;" ::: "memory")
#define CP_WAIT(n)  asm volatile("cp.async.wait_group %0;" :: "n"(n) : "memory")

__device__ __forceinline__ void ldsm4(uint32_t* r, uint32_t addr) {
    asm volatile("ldmatrix.sync.aligned.m8n8.x4.shared.b16 {%0,%1,%2,%3}, [%4];"
                 : "=r"(r[0]), "=r"(r[1]), "=r"(r[2]), "=r"(r[3]) : "r"(addr));
}
__device__ __forceinline__ void mma16816(float* c, const uint32_t* a, const uint32_t* b) {
    asm volatile("mma.sync.aligned.m16n8k16.row.col.f32.f16.f16.f32 "
                 "{%0,%1,%2,%3}, {%4,%5,%6,%7}, {%8,%9}, {%0,%1,%2,%3};"
                 : "+f"(c[0]), "+f"(c[1]), "+f"(c[2]), "+f"(c[3])
                 : "r"(a[0]), "r"(a[1]), "r"(a[2]), "r"(a[3]), "r"(b[0]), "r"(b[1]));
}
__device__ __forceinline__ float fast_tanh(float x) {
    float t = __expf(2.0f * x);
    return (t - 1.0f) / (t + 1.0f);
}
__device__ __forceinline__ float fast_sigmoid(float x) {
    return 1.0f / (1.0f + __expf(-x));
}

// ---------------- prep kernels ----------------
__global__ void prep_x_kernel(const float4* __restrict__ x4) {
    size_t i = (size_t)blockIdx.x * 256 + threadIdx.x;      // 8388608 threads
    float4 f = x4[i];
    float a[4] = {f.x, f.y, f.z, f.w};
    unsigned short hs[4], ls[4];
#pragma unroll
    for (int j = 0; j < 4; j++) {
        __half h = __float2half_rn(a[j]);
        float hf = __half2float(h);
        __half lo = __float2half_rn(a[j] - hf);
        hs[j] = __half_as_ushort(h);
        ls[j] = __half_as_ushort(lo);
    }
    uint2 hh = make_uint2((uint32_t)hs[0] | ((uint32_t)hs[1] << 16),
                          (uint32_t)hs[2] | ((uint32_t)hs[3] << 16));
    uint2 ll = make_uint2((uint32_t)ls[0] | ((uint32_t)ls[1] << 16),
                          (uint32_t)ls[2] | ((uint32_t)ls[3] << 16));
    size_t o = i * 4;
    *(uint2*)(g_xh + o) = hh;
    *(uint2*)(g_xl + o) = ll;
}

__global__ void prep_vu_kernel(const float* __restrict__ v, const float* __restrict__ u) {
    int gid = blockIdx.x * 256 + threadIdx.x;               // 524288 threads
    int k = gid & (IN_DIM - 1);
    int l = gid >> 10;
    size_t o = (size_t)l * IN_DIM + k;
    g_v[o] = __float2half_rn(v[(size_t)k * L_DIM + l]);
    g_u[o] = __float2half_rn(u[(size_t)k * L_DIM + l]);
}

// ---------------- main fused GEMM kernel ----------------
// One CTA per (instance n, l-chunk lc). 512 threads / 16 warps.
// Warp tile 32 M x 64 N: mw = wid&3 (rows), nw = wid>>2 (cols; <2: V, >=2: U).
// SMEM map (bytes):
#define SM_W      0          // 128 f32 = 512
#define SM_RED    512        // 256 f32 = 1024
#define SM_STASH  1536       // 128 rows x 264B (fp16, padded) -> ends 35328
#define STASH_STRIDE 264
#define SM_TILES  35328      // 3 stages x 32KB
#define BUF_STRIDE 32768     // per stage: A_hi 8K, A_lo 8K, B 16K
#define OFF_A_HI  0
#define OFF_A_LO  8192
#define OFF_B     16384
#define SM_TOTAL  (SM_TILES + 3 * BUF_STRIDE)   // 133632

#define BK 32
#define NI (IN_DIM / BK)     // 32 K-iterations

__global__ void __launch_bounds__(512, 1)
mil_gemm_kernel(const float* __restrict__ w)
{
    extern __shared__ char smem[];
    const int task = blockIdx.x;       // 0..1023
    const int n    = task >> 2;
    const int lc   = task & 3;
    const int l0   = lc * 128;
    const int tid  = threadIdx.x;
    const int lane = tid & 31;
    const int wid  = tid >> 5;
    const int mw   = wid & 3;    // M band: rows mw*32..+31
    const int nw   = wid >> 2;   // N band: combined cols nw*64..+63 (nw<2: V, nw>=2: U)
    const uint32_t smem_base = smem_u32(smem);

    // w slice for this l-chunk into smem
    float* ws = (float*)(smem + SM_W);
    if (tid < 128) ws[tid] = w[l0 + tid];

    const __half* xh = g_xh + (size_t)n * BATCH * IN_DIM;
    const __half* xl = g_xl + (size_t)n * BATCH * IN_DIM;
    const size_t lofs = (size_t)l0 * IN_DIM;

    // ---- per-thread cp.async assignments ----
    // A: 1024 16B chunks (hi 0-511, lo 512-1023); each thread 2
    const __half* srcA[2];
    uint32_t dstA[2];
#pragma unroll
    for (int j = 0; j < 2; j++) {
        int a_idx = j * 512 + tid;
        int hilo  = a_idx >> 9;
        int rs    = a_idx & 511;
        int arow  = rs >> 2;
        int aseg  = rs & 3;
        srcA[j] = (hilo ? xl : xh) + (size_t)arow * IN_DIM + aseg * 8;
        dstA[j] = SM_TILES + (hilo ? OFF_A_LO : OFF_A_HI) + SWZ64(arow * 64 + aseg * 16);
    }
    // B: 1024 chunks; rows 0-127 = V, 128-255 = U; each thread 2
    const __half* srcB[2];
    uint32_t dstB[2];
#pragma unroll
    for (int j = 0; j < 2; j++) {
        int b_idx = j * 512 + tid;
        int brow  = b_idx >> 2;          // 0..255
        int bseg  = b_idx & 3;
        const __half* mat = (brow < 128) ? g_v : g_u;
        srcB[j] = mat + lofs + (size_t)(brow & 127) * IN_DIM + bseg * 8;
        dstB[j] = SM_TILES + OFF_B + SWZ64(brow * 64 + bseg * 16);
    }

    float acc[2][8][4];
#pragma unroll
    for (int mt = 0; mt < 2; mt++)
#pragma unroll
        for (int nt = 0; nt < 8; nt++)
#pragma unroll
            for (int r = 0; r < 4; r++) acc[mt][nt][r] = 0.f;

    // ---- prologue: stages 0 and 1 ----
#pragma unroll
    for (int s = 0; s < 2; s++) {
        uint32_t bb = smem_base + s * BUF_STRIDE;
        int k0 = s * BK;
#pragma unroll
        for (int j = 0; j < 2; j++) CP16(bb + dstA[j], srcA[j] + k0);
#pragma unroll
        for (int j = 0; j < 2; j++) CP16(bb + dstB[j], srcB[j] + k0);
        CP_COMMIT();
    }

    int slot = 0, nslot = 2;
    for (int it = 0; it < NI; it++) {
        if (it + 1 < NI) { CP_WAIT(1); } else { CP_WAIT(0); }
        __syncthreads();
        if (it + 2 < NI) {
            uint32_t bb = smem_base + nslot * BUF_STRIDE;
            int k0 = (it + 2) * BK;
#pragma unroll
            for (int j = 0; j < 2; j++) CP16(bb + dstA[j], srcA[j] + k0);
#pragma unroll
            for (int j = 0; j < 2; j++) CP16(bb + dstB[j], srcB[j] + k0);
            CP_COMMIT();
            nslot = (nslot == 2) ? 0 : nslot + 1;
        }

        const uint32_t bb = smem_base + slot * BUF_STRIDE;
        slot = (slot == 2) ? 0 : slot + 1;
        const uint32_t aHi = bb + SM_TILES + OFF_A_HI;
        const uint32_t aLo = bb + SM_TILES + OFF_A_LO;
        const uint32_t bB  = bb + SM_TILES + OFF_B;

#pragma unroll
        for (int ks = 0; ks < 2; ks++) {
            // A fragments: row = mw*32 + mt*16 + (lane&15), k-half = (lane>>4)*8
            uint32_t ah[2][4], al[2][4];
            const uint32_t akoff = ks * 32 + (lane >> 4) * 16;
#pragma unroll
            for (int mt = 0; mt < 2; mt++) {
                uint32_t rowb = (mw * 32 + mt * 16 + (lane & 15)) * 64;
                uint32_t so = SWZ64(rowb + akoff);
                ldsm4(ah[mt], aHi + so);
                ldsm4(al[mt], aLo + so);
            }
            const uint32_t bkoff = ks * 32 + ((lane >> 3) & 1) * 16;
#pragma unroll
            for (int ntp = 0; ntp < 4; ntp++) {
                uint32_t rowb = (nw * 64 + ntp * 16 + ((lane >> 4) & 1) * 8 + (lane & 7)) * 64;
                uint32_t so = SWZ64(rowb + bkoff);
                uint32_t bf[4];
                ldsm4(bf, bB + so);
#pragma unroll
                for (int half = 0; half < 2; half++) {
                    int nt = ntp * 2 + half;
                    // term-major: same acc revisited every 2 MMAs (hi term, then lo term)
#pragma unroll
                    for (int mt = 0; mt < 2; mt++)
                        mma16816(acc[mt][nt], ah[mt], bf + half * 2);
#pragma unroll
                    for (int mt = 0; mt < 2; mt++)
                        mma16816(acc[mt][nt], al[mt], bf + half * 2);
                }
            }
        }
    }
    __syncthreads();

    // ---- epilogue ----
    if (nw < 2) {
        // V warps: stash tanh as fp16
#pragma unroll
        for (int mt = 0; mt < 2; mt++)
#pragma unroll
            for (int nt = 0; nt < 8; nt++) {
                int col = nw * 64 + nt * 8 + (lane & 3) * 2;
#pragma unroll
                for (int half = 0; half < 2; half++) {
                    int row = mw * 32 + mt * 16 + half * 8 + (lane >> 2);
                    float h0 = fast_tanh(acc[mt][nt][half * 2 + 0]);
                    float h1 = fast_tanh(acc[mt][nt][half * 2 + 1]);
                    *(__half2*)(smem + SM_STASH + row * STASH_STRIDE + col * 2) =
                        __floats2half2_rn(h0, h1);
                }
            }
    }
    __syncthreads();

    float rowacc[4] = {0.f, 0.f, 0.f, 0.f};
    if (nw >= 2) {
        // U warps: gate + weight
#pragma unroll
        for (int mt = 0; mt < 2; mt++)
#pragma unroll
            for (int nt = 0; nt < 8; nt++) {
                int vcol = (nw - 2) * 64 + nt * 8 + (lane & 3) * 2;
                float w0 = ws[vcol + 0];
                float w1 = ws[vcol + 1];
#pragma unroll
                for (int half = 0; half < 2; half++) {
                    int row = mw * 32 + mt * 16 + half * 8 + (lane >> 2);
                    __half2 hh = *(const __half2*)(smem + SM_STASH +
                                                   row * STASH_STRIDE + vcol * 2);
                    float g0 = fast_sigmoid(acc[mt][nt][half * 2 + 0]);
                    float g1 = fast_sigmoid(acc[mt][nt][half * 2 + 1]);
                    rowacc[mt * 2 + half] += __low2float(hh)  * g0 * w0 +
                                             __high2float(hh) * g1 * w1;
                }
            }
    }
    __syncthreads();

    // ---- final reduction: 8 U warps -> 128 partial scores ----
    float* red = (float*)(smem + SM_RED);
    if (nw >= 2) {
#pragma unroll
        for (int ri = 0; ri < 4; ri++) {
            float p = rowacc[ri];
            p += __shfl_xor_sync(0xffffffffu, p, 1);
            p += __shfl_xor_sync(0xffffffffu, p, 2);
            if ((lane & 3) == 0) {
                int row = mw * 32 + (ri >> 1) * 16 + (ri & 1) * 8 + (lane >> 2);
                red[(nw - 2) * 128 + row] = p;
            }
        }
    }
    __syncthreads();
    if (tid < BATCH)
        g_part[(size_t)task * BATCH + tid] = red[tid] + red[128 + tid];
}

// ---------------- softmax over instance axis (sums 4 l-chunk partials) ----------------
__global__ void softmax_kernel(float* __restrict__ out)
{
    const int b   = blockIdx.x;    // 0..127
    const int tid = threadIdx.x;   // 0..255 == n
    __shared__ float sh[256];

    const float* p = g_part + ((size_t)tid * 4) * BATCH + b;
    float s = p[0] + p[BATCH] + p[2 * BATCH] + p[3 * BATCH];
    sh[tid] = s;
    __syncthreads();
#pragma unroll
    for (int off = 128; off > 0; off >>= 1) {
        if (tid < off) sh[tid] = fmaxf(sh[tid], sh[tid + off]);
        __syncthreads();
    }
    float m = sh[0];
    __syncthreads();
    float e = __expf(s - m);
    sh[tid] = e;
    __syncthreads();
#pragma unroll
    for (int off = 128; off > 0; off >>= 1) {
        if (tid < off) sh[tid] += sh[tid + off];
        __syncthreads();
    }
    out[(size_t)tid * BATCH + b] = e / sh[0];
}

extern "C" void kernel_launch(void* const* d_in, const int* in_sizes, int n_in,
                              void* d_out, int out_size)
{
    const float* x = (const float*)d_in[0];
    const float* v = (const float*)d_in[1];
    const float* u = (const float*)d_in[2];
    const float* w = (const float*)d_in[3];
    float* out = (float*)d_out;

    cudaFuncSetAttribute(mil_gemm_kernel,
                         cudaFuncAttributeMaxDynamicSharedMemorySize, SM_TOTAL);

    prep_x_kernel<<<32768, 256>>>((const float4*)x);
    prep_vu_kernel<<<2048, 256>>>(v, u);
    mil_gemm_kernel<<<1024, 512, SM_TOTAL>>>(w);
    softmax_kernel<<<BATCH, 256>>>(out);
}

// round 8
// speedup vs baseline: 3.0315x; 1.5006x over previous
#include <cuda_runtime.h>
#include <cuda_fp16.h>
#include <cstdint>
#include <math.h>

#define N_INST 256
#define BATCH  128
#define IN_DIM 1024
#define L_DIM  512

// ---------------- device scratch (allocation-free rule) ----------------
__device__ __align__(256) __half g_x[(size_t)N_INST * BATCH * IN_DIM]; // 64MB fp16
__device__ __align__(256) __half g_v[L_DIM * IN_DIM];  // [l][k] transposed, fp16
__device__ __align__(256) __half g_u[L_DIM * IN_DIM];
__device__ float g_part[1024 * BATCH];   // partial scores per (instance, l-chunk)

// ---------------- helpers ----------------
__device__ __forceinline__ uint32_t smem_u32(const void* p) {
    uint32_t a;
    asm("{ .reg .u64 t; cvta.to.shared.u64 t, %1; cvt.u32.u64 %0, t; }" : "=r"(a) : "l"(p));
    return a;
}
// 64B-row swizzle: XOR row bits [8:7] into 16B-chunk bits [5:4]
#define SWZ64(off) ((off) ^ (((off) >> 3) & 0x30))

#define CP16(dst, src) \
    asm volatile("cp.async.cg.shared.global [%0], [%1], 16;" :: "r"(dst), "l"(src))
#define CP_COMMIT() asm volatile("cp.async.commit_group;" ::: "memory")
#define CP_WAIT(n)  asm volatile("cp.async.wait_group %0;" :: "n"(n) : "memory")

__device__ __forceinline__ void ldsm4(uint32_t* r, uint32_t addr) {
    asm volatile("ldmatrix.sync.aligned.m8n8.x4.shared.b16 {%0,%1,%2,%3}, [%4];"
                 : "=r"(r[0]), "=r"(r[1]), "=r"(r[2]), "=r"(r[3]) : "r"(addr));
}
__device__ __forceinline__ void mma16816(float* c, const uint32_t* a, const uint32_t* b) {
    asm volatile("mma.sync.aligned.m16n8k16.row.col.f32.f16.f16.f32 "
                 "{%0,%1,%2,%3}, {%4,%5,%6,%7}, {%8,%9}, {%0,%1,%2,%3};"
                 : "+f"(c[0]), "+f"(c[1]), "+f"(c[2]), "+f"(c[3])
                 : "r"(a[0]), "r"(a[1]), "r"(a[2]), "r"(a[3]), "r"(b[0]), "r"(b[1]));
}
__device__ __forceinline__ float fast_tanh(float x) {
    float t = __expf(2.0f * x);
    return (t - 1.0f) / (t + 1.0f);
}
__device__ __forceinline__ float fast_sigmoid(float x) {
    return 1.0f / (1.0f + __expf(-x));
}

// ---------------- prep kernels ----------------
__global__ void prep_x_kernel(const float4* __restrict__ x4) {
    size_t i = (size_t)blockIdx.x * 256 + threadIdx.x;      // 8388608 threads
    float4 f = x4[i];
    __half2 h01 = __floats2half2_rn(f.x, f.y);
    __half2 h23 = __floats2half2_rn(f.z, f.w);
    size_t o = i * 4;
    __half2* dst = (__half2*)(g_x + o);
    dst[0] = h01;
    dst[1] = h23;
}

__global__ void prep_vu_kernel(const float* __restrict__ v, const float* __restrict__ u) {
    int gid = blockIdx.x * 256 + threadIdx.x;               // 524288 threads
    int k = gid & (IN_DIM - 1);
    int l = gid >> 10;
    size_t o = (size_t)l * IN_DIM + k;
    g_v[o] = __float2half_rn(v[(size_t)k * L_DIM + l]);
    g_u[o] = __float2half_rn(u[(size_t)k * L_DIM + l]);
}

// ---------------- main fused GEMM kernel ----------------
// One CTA per (instance n, l-chunk lc). 512 threads / 16 warps.
// Warp tile 32 M x 64 N: mw = wid&3 (rows), nw = wid>>2 (cols; <2: V, >=2: U).
// SMEM map (bytes):
#define SM_W      0          // 128 f32 = 512
#define SM_RED    512        // 256 f32 = 1024
#define SM_STASH  1536       // 128 rows x 264B (fp16, padded) -> ends 35328
#define STASH_STRIDE 264
#define SM_TILES  35328      // 3 stages x 24KB
#define BUF_STRIDE 24576     // per stage: A 8K, B 16K
#define OFF_A     0
#define OFF_B     8192
#define SM_TOTAL  (SM_TILES + 3 * BUF_STRIDE)   // 109056

#define BK 32
#define NI (IN_DIM / BK)     // 32 K-iterations

__global__ void __launch_bounds__(512, 1)
mil_gemm_kernel(const float* __restrict__ w)
{
    extern __shared__ char smem[];
    const int task = blockIdx.x;       // 0..1023
    const int n    = task >> 2;
    const int lc   = task & 3;
    const int l0   = lc * 128;
    const int tid  = threadIdx.x;
    const int lane = tid & 31;
    const int wid  = tid >> 5;
    const int mw   = wid & 3;    // M band: rows mw*32..+31
    const int nw   = wid >> 2;   // N band: combined cols nw*64..+63 (nw<2: V, nw>=2: U)
    const uint32_t smem_base = smem_u32(smem);

    // w slice for this l-chunk into smem
    float* ws = (float*)(smem + SM_W);
    if (tid < 128) ws[tid] = w[l0 + tid];

    const __half* xp = g_x + (size_t)n * BATCH * IN_DIM;
    const size_t lofs = (size_t)l0 * IN_DIM;

    // ---- per-thread cp.async assignments ----
    // A: 512 16B chunks; each thread 1
    const int arow = tid >> 2;          // 0..127
    const int aseg = tid & 3;
    const __half* srcA = xp + (size_t)arow * IN_DIM + aseg * 8;
    const uint32_t dstA = SM_TILES + OFF_A + SWZ64(arow * 64 + aseg * 16);

    // B: 1024 chunks; rows 0-127 = V, 128-255 = U; each thread 2
    const __half* srcB[2];
    uint32_t dstB[2];
#pragma unroll
    for (int j = 0; j < 2; j++) {
        int b_idx = j * 512 + tid;
        int brow  = b_idx >> 2;          // 0..255
        int bseg  = b_idx & 3;
        const __half* mat = (brow < 128) ? g_v : g_u;
        srcB[j] = mat + lofs + (size_t)(brow & 127) * IN_DIM + bseg * 8;
        dstB[j] = SM_TILES + OFF_B + SWZ64(brow * 64 + bseg * 16);
    }

    float acc[2][8][4];
#pragma unroll
    for (int mt = 0; mt < 2; mt++)
#pragma unroll
        for (int nt = 0; nt < 8; nt++)
#pragma unroll
            for (int r = 0; r < 4; r++) acc[mt][nt][r] = 0.f;

    // ---- prologue: stages 0 and 1 ----
#pragma unroll
    for (int s = 0; s < 2; s++) {
        uint32_t bb = smem_base + s * BUF_STRIDE;
        int k0 = s * BK;
        CP16(bb + dstA, srcA + k0);
#pragma unroll
        for (int j = 0; j < 2; j++) CP16(bb + dstB[j], srcB[j] + k0);
        CP_COMMIT();
    }

    int slot = 0, nslot = 2;
    for (int it = 0; it < NI; it++) {
        if (it + 1 < NI) { CP_WAIT(1); } else { CP_WAIT(0); }
        __syncthreads();
        if (it + 2 < NI) {
            uint32_t bb = smem_base + nslot * BUF_STRIDE;
            int k0 = (it + 2) * BK;
            CP16(bb + dstA, srcA + k0);
#pragma unroll
            for (int j = 0; j < 2; j++) CP16(bb + dstB[j], srcB[j] + k0);
            CP_COMMIT();
            nslot = (nslot == 2) ? 0 : nslot + 1;
        }

        const uint32_t bb = smem_base + slot * BUF_STRIDE;
        slot = (slot == 2) ? 0 : slot + 1;
        const uint32_t aA = bb + SM_TILES + OFF_A;
        const uint32_t bB = bb + SM_TILES + OFF_B;

#pragma unroll
        for (int ks = 0; ks < 2; ks++) {
            // A fragments: row = mw*32 + mt*16 + (lane&15), k-half = (lane>>4)*8
            uint32_t af[2][4];
            const uint32_t akoff = ks * 32 + (lane >> 4) * 16;
#pragma unroll
            for (int mt = 0; mt < 2; mt++) {
                uint32_t rowb = (mw * 32 + mt * 16 + (lane & 15)) * 64;
                ldsm4(af[mt], aA + SWZ64(rowb + akoff));
            }
            const uint32_t bkoff = ks * 32 + ((lane >> 3) & 1) * 16;
#pragma unroll
            for (int ntp = 0; ntp < 4; ntp++) {
                uint32_t rowb = (nw * 64 + ntp * 16 + ((lane >> 4) & 1) * 8 + (lane & 7)) * 64;
                uint32_t bf[4];
                ldsm4(bf, bB + SWZ64(rowb + bkoff));
#pragma unroll
                for (int half = 0; half < 2; half++) {
                    int nt = ntp * 2 + half;
#pragma unroll
                    for (int mt = 0; mt < 2; mt++)
                        mma16816(acc[mt][nt], af[mt], bf + half * 2);
                }
            }
        }
    }
    __syncthreads();

    // ---- epilogue ----
    if (nw < 2) {
        // V warps: stash tanh as fp16
#pragma unroll
        for (int mt = 0; mt < 2; mt++)
#pragma unroll
            for (int nt = 0; nt < 8; nt++) {
                int col = nw * 64 + nt * 8 + (lane & 3) * 2;
#pragma unroll
                for (int half = 0; half < 2; half++) {
                    int row = mw * 32 + mt * 16 + half * 8 + (lane >> 2);
                    float h0 = fast_tanh(acc[mt][nt][half * 2 + 0]);
                    float h1 = fast_tanh(acc[mt][nt][half * 2 + 1]);
                    *(__half2*)(smem + SM_STASH + row * STASH_STRIDE + col * 2) =
                        __floats2half2_rn(h0, h1);
                }
            }
    }
    __syncthreads();

    float rowacc[4] = {0.f, 0.f, 0.f, 0.f};
    if (nw >= 2) {
        // U warps: gate + weight
#pragma unroll
        for (int mt = 0; mt < 2; mt++)
#pragma unroll
            for (int nt = 0; nt < 8; nt++) {
                int vcol = (nw - 2) * 64 + nt * 8 + (lane & 3) * 2;
                float w0 = ws[vcol + 0];
                float w1 = ws[vcol + 1];
#pragma unroll
                for (int half = 0; half < 2; half++) {
                    int row = mw * 32 + mt * 16 + half * 8 + (lane >> 2);
                    __half2 hh = *(const __half2*)(smem + SM_STASH +
                                                   row * STASH_STRIDE + vcol * 2);
                    float g0 = fast_sigmoid(acc[mt][nt][half * 2 + 0]);
                    float g1 = fast_sigmoid(acc[mt][nt][half * 2 + 1]);
                    rowacc[mt * 2 + half] += __low2float(hh)  * g0 * w0 +
                                             __high2float(hh) * g1 * w1;
                }
            }
    }
    __syncthreads();

    // ---- final reduction: 8 U warps -> 128 partial scores ----
    float* red = (float*)(smem + SM_RED);
    if (nw >= 2) {
#pragma unroll
        for (int ri = 0; ri < 4; ri++) {
            float p = rowacc[ri];
            p += __shfl_xor_sync(0xffffffffu, p, 1);
            p += __shfl_xor_sync(0xffffffffu, p, 2);
            if ((lane & 3) == 0) {
                int row = mw * 32 + (ri >> 1) * 16 + (ri & 1) * 8 + (lane >> 2);
                red[(nw - 2) * 128 + row] = p;
            }
        }
    }
    __syncthreads();
    if (tid < BATCH)
        g_part[(size_t)task * BATCH + tid] = red[tid] + red[128 + tid];
}

// ---------------- softmax over instance axis (sums 4 l-chunk partials) ----------------
__global__ void softmax_kernel(float* __restrict__ out)
{
    const int b   = blockIdx.x;    // 0..127
    const int tid = threadIdx.x;   // 0..255 == n
    __shared__ float sh[256];

    const float* p = g_part + ((size_t)tid * 4) * BATCH + b;
    float s = p[0] + p[BATCH] + p[2 * BATCH] + p[3 * BATCH];
    sh[tid] = s;
    __syncthreads();
#pragma unroll
    for (int off = 128; off > 0; off >>= 1) {
        if (tid < off) sh[tid] = fmaxf(sh[tid], sh[tid + off]);
        __syncthreads();
    }
    float m = sh[0];
    __syncthreads();
    float e = __expf(s - m);
    sh[tid] = e;
    __syncthreads();
#pragma unroll
    for (int off = 128; off > 0; off >>= 1) {
        if (tid < off) sh[tid] += sh[tid + off];
        __syncthreads();
    }
    out[(size_t)tid * BATCH + b] = e / sh[0];
}

extern "C" void kernel_launch(void* const* d_in, const int* in_sizes, int n_in,
                              void* d_out, int out_size)
{
    const float* x = (const float*)d_in[0];
    const float* v = (const float*)d_in[1];
    const float* u = (const float*)d_in[2];
    const float* w = (const float*)d_in[3];
    float* out = (float*)d_out;

    cudaFuncSetAttribute(mil_gemm_kernel,
                         cudaFuncAttributeMaxDynamicSharedMemorySize, SM_TOTAL);

    prep_x_kernel<<<32768, 256>>>((const float4*)x);
    prep_vu_kernel<<<2048, 256>>>(v, u);
    mil_gemm_kernel<<<1024, 512, SM_TOTAL>>>(w);
    softmax_kernel<<<BATCH, 256>>>(out);
}

// round 9
// speedup vs baseline: 3.3136x; 1.0931x over previous
#include <cuda_runtime.h>
#include <cuda_fp16.h>
#include <cstdint>
#include <math.h>

#define N_INST 256
#define BATCH  128
#define IN_DIM 1024
#define L_DIM  512

// ---------------- device scratch (allocation-free rule) ----------------
__device__ __align__(256) __half g_x[(size_t)N_INST * BATCH * IN_DIM]; // 64MB fp16
__device__ __align__(256) __half g_v[L_DIM * IN_DIM];  // [l][k] transposed, fp16
__device__ __align__(256) __half g_u[L_DIM * IN_DIM];
__device__ float g_part[1024 * BATCH];   // partial scores per (instance, l-chunk)

// ---------------- helpers ----------------
__device__ __forceinline__ uint32_t smem_u32(const void* p) {
    uint32_t a;
    asm("{ .reg .u64 t; cvta.to.shared.u64 t, %1; cvt.u32.u64 %0, t; }" : "=r"(a) : "l"(p));
    return a;
}
// 128B-row swizzle (SW128): XOR row bits [9:7] into 16B-chunk bits [6:4]
#define SWZ128(off) ((off) ^ (((off) >> 3) & 0x70))

#define CP16(dst, src) \
    asm volatile("cp.async.cg.shared.global [%0], [%1], 16;" :: "r"(dst), "l"(src))
#define CP_COMMIT() asm volatile("cp.async.commit_group;" ::: "memory")
#define CP_WAIT(n)  asm volatile("cp.async.wait_group %0;" :: "n"(n) : "memory")

__device__ __forceinline__ void ldsm4(uint32_t* r, uint32_t addr) {
    asm volatile("ldmatrix.sync.aligned.m8n8.x4.shared.b16 {%0,%1,%2,%3}, [%4];"
                 : "=r"(r[0]), "=r"(r[1]), "=r"(r[2]), "=r"(r[3]) : "r"(addr));
}
__device__ __forceinline__ void mma16816(float* c, const uint32_t* a, const uint32_t* b) {
    asm volatile("mma.sync.aligned.m16n8k16.row.col.f32.f16.f16.f32 "
                 "{%0,%1,%2,%3}, {%4,%5,%6,%7}, {%8,%9}, {%0,%1,%2,%3};"
                 : "+f"(c[0]), "+f"(c[1]), "+f"(c[2]), "+f"(c[3])
                 : "r"(a[0]), "r"(a[1]), "r"(a[2]), "r"(a[3]), "r"(b[0]), "r"(b[1]));
}
__device__ __forceinline__ float fast_tanh(float x) {
    float t = __expf(2.0f * x);
    return (t - 1.0f) / (t + 1.0f);
}
__device__ __forceinline__ float fast_sigmoid(float x) {
    return 1.0f / (1.0f + __expf(-x));
}

// ---------------- prep kernels ----------------
__global__ void prep_x_kernel(const float4* __restrict__ x4) {
    size_t i = (size_t)blockIdx.x * 256 + threadIdx.x;      // 8388608 threads
    float4 f = x4[i];
    __half2 h01 = __floats2half2_rn(f.x, f.y);
    __half2 h23 = __floats2half2_rn(f.z, f.w);
    size_t o = i * 4;
    __half2* dst = (__half2*)(g_x + o);
    dst[0] = h01;
    dst[1] = h23;
}

__global__ void prep_vu_kernel(const float* __restrict__ v, const float* __restrict__ u) {
    int gid = blockIdx.x * 256 + threadIdx.x;               // 524288 threads
    int k = gid & (IN_DIM - 1);
    int l = gid >> 10;
    size_t o = (size_t)l * IN_DIM + k;
    g_v[o] = __float2half_rn(v[(size_t)k * L_DIM + l]);
    g_u[o] = __float2half_rn(u[(size_t)k * L_DIM + l]);
}

// ---------------- main fused GEMM kernel ----------------
// One CTA per (instance n, l-chunk lc). 512 threads / 16 warps.
// Warp tile 32 M x 64 N: mw = wid&3 (rows), nw = wid>>2 (cols; <2: V, >=2: U).
// BK=64: 4 k-steps per pipeline stage, 16 iterations total.
// SMEM map (bytes):
#define SM_W      0          // 128 f32 = 512
#define SM_RED    512        // 256 f32 = 1024
#define SM_STASH  1536       // 128 rows x 264B (fp16, padded) -> ends 35328
#define STASH_STRIDE 264
#define SM_TILES  35328      // 3 stages x 48KB
#define BUF_STRIDE 49152     // per stage: A 16K (128 rows x 128B), B 32K (256 rows x 128B)
#define OFF_A     0
#define OFF_B     16384
#define SM_TOTAL  (SM_TILES + 3 * BUF_STRIDE)   // 182784

#define BK 64
#define NI (IN_DIM / BK)     // 16 K-iterations

__global__ void __launch_bounds__(512, 1)
mil_gemm_kernel(const float* __restrict__ w)
{
    extern __shared__ char smem[];
    const int task = blockIdx.x;       // 0..1023
    const int n    = task >> 2;
    const int lc   = task & 3;
    const int l0   = lc * 128;
    const int tid  = threadIdx.x;
    const int lane = tid & 31;
    const int wid  = tid >> 5;
    const int mw   = wid & 3;    // M band: rows mw*32..+31
    const int nw   = wid >> 2;   // N band: combined cols nw*64..+63 (nw<2: V, nw>=2: U)
    const uint32_t smem_base = smem_u32(smem);

    // w slice for this l-chunk into smem
    float* ws = (float*)(smem + SM_W);
    if (tid < 128) ws[tid] = w[l0 + tid];

    const __half* xp = g_x + (size_t)n * BATCH * IN_DIM;
    const size_t lofs = (size_t)l0 * IN_DIM;

    // ---- per-thread cp.async assignments (per stage: A 1024 + B 2048 chunks) ----
    // A: 128 rows x 8 chunks; each thread 2
    const __half* srcA[2];
    uint32_t dstA[2];
#pragma unroll
    for (int j = 0; j < 2; j++) {
        int idx  = j * 512 + tid;
        int row  = idx >> 3;
        int seg  = idx & 7;
        srcA[j] = xp + (size_t)row * IN_DIM + seg * 8;
        dstA[j] = SM_TILES + OFF_A + SWZ128(row * 128 + seg * 16);
    }
    // B: 256 rows (0-127 V, 128-255 U) x 8 chunks; each thread 4
    const __half* srcB[4];
    uint32_t dstB[4];
#pragma unroll
    for (int j = 0; j < 4; j++) {
        int idx  = j * 512 + tid;
        int brow = idx >> 3;
        int seg  = idx & 7;
        const __half* mat = (brow < 128) ? g_v : g_u;
        srcB[j] = mat + lofs + (size_t)(brow & 127) * IN_DIM + seg * 8;
        dstB[j] = SM_TILES + OFF_B + SWZ128(brow * 128 + seg * 16);
    }

    float acc[2][8][4];
#pragma unroll
    for (int mt = 0; mt < 2; mt++)
#pragma unroll
        for (int nt = 0; nt < 8; nt++)
#pragma unroll
            for (int r = 0; r < 4; r++) acc[mt][nt][r] = 0.f;

    // ---- prologue: stages 0 and 1 ----
#pragma unroll
    for (int s = 0; s < 2; s++) {
        uint32_t bb = smem_base + s * BUF_STRIDE;
        int k0 = s * BK;
#pragma unroll
        for (int j = 0; j < 2; j++) CP16(bb + dstA[j], srcA[j] + k0);
#pragma unroll
        for (int j = 0; j < 4; j++) CP16(bb + dstB[j], srcB[j] + k0);
        CP_COMMIT();
    }

    int slot = 0, nslot = 2;
    for (int it = 0; it < NI; it++) {
        if (it + 1 < NI) { CP_WAIT(1); } else { CP_WAIT(0); }
        __syncthreads();
        if (it + 2 < NI) {
            uint32_t bb = smem_base + nslot * BUF_STRIDE;
            int k0 = (it + 2) * BK;
#pragma unroll
            for (int j = 0; j < 2; j++) CP16(bb + dstA[j], srcA[j] + k0);
#pragma unroll
            for (int j = 0; j < 4; j++) CP16(bb + dstB[j], srcB[j] + k0);
            CP_COMMIT();
            nslot = (nslot == 2) ? 0 : nslot + 1;
        }

        const uint32_t bb = smem_base + slot * BUF_STRIDE;
        slot = (slot == 2) ? 0 : slot + 1;
        const uint32_t aA = bb + SM_TILES + OFF_A;
        const uint32_t bB = bb + SM_TILES + OFF_B;

#pragma unroll
        for (int ks = 0; ks < 4; ks++) {
            // A fragments: row = mw*32 + mt*16 + (lane&15), k-half = (lane>>4)*8
            uint32_t af[2][4];
            const uint32_t akoff = ks * 32 + (lane >> 4) * 16;
#pragma unroll
            for (int mt = 0; mt < 2; mt++) {
                uint32_t rowb = (mw * 32 + mt * 16 + (lane & 15)) * 128;
                ldsm4(af[mt], aA + SWZ128(rowb + akoff));
            }
            const uint32_t bkoff = ks * 32 + ((lane >> 3) & 1) * 16;
#pragma unroll
            for (int ntp = 0; ntp < 4; ntp++) {
                uint32_t rowb = (nw * 64 + ntp * 16 + ((lane >> 4) & 1) * 8 + (lane & 7)) * 128;
                uint32_t bf[4];
                ldsm4(bf, bB + SWZ128(rowb + bkoff));
#pragma unroll
                for (int half = 0; half < 2; half++) {
                    int nt = ntp * 2 + half;
#pragma unroll
                    for (int mt = 0; mt < 2; mt++)
                        mma16816(acc[mt][nt], af[mt], bf + half * 2);
                }
            }
        }
    }
    __syncthreads();

    // ---- epilogue ----
    if (nw < 2) {
        // V warps: stash tanh as fp16
#pragma unroll
        for (int mt = 0; mt < 2; mt++)
#pragma unroll
            for (int nt = 0; nt < 8; nt++) {
                int col = nw * 64 + nt * 8 + (lane & 3) * 2;
#pragma unroll
                for (int half = 0; half < 2; half++) {
                    int row = mw * 32 + mt * 16 + half * 8 + (lane >> 2);
                    float h0 = fast_tanh(acc[mt][nt][half * 2 + 0]);
                    float h1 = fast_tanh(acc[mt][nt][half * 2 + 1]);
                    *(__half2*)(smem + SM_STASH + row * STASH_STRIDE + col * 2) =
                        __floats2half2_rn(h0, h1);
                }
            }
    }
    __syncthreads();

    float rowacc[4] = {0.f, 0.f, 0.f, 0.f};
    if (nw >= 2) {
        // U warps: gate + weight
#pragma unroll
        for (int mt = 0; mt < 2; mt++)
#pragma unroll
            for (int nt = 0; nt < 8; nt++) {
                int vcol = (nw - 2) * 64 + nt * 8 + (lane & 3) * 2;
                float w0 = ws[vcol + 0];
                float w1 = ws[vcol + 1];
#pragma unroll
                for (int half = 0; half < 2; half++) {
                    int row = mw * 32 + mt * 16 + half * 8 + (lane >> 2);
                    __half2 hh = *(const __half2*)(smem + SM_STASH +
                                                   row * STASH_STRIDE + vcol * 2);
                    float g0 = fast_sigmoid(acc[mt][nt][half * 2 + 0]);
                    float g1 = fast_sigmoid(acc[mt][nt][half * 2 + 1]);
                    rowacc[mt * 2 + half] += __low2float(hh)  * g0 * w0 +
                                             __high2float(hh) * g1 * w1;
                }
            }
    }
    __syncthreads();

    // ---- final reduction: 8 U warps -> 128 partial scores ----
    float* red = (float*)(smem + SM_RED);
    if (nw >= 2) {
#pragma unroll
        for (int ri = 0; ri < 4; ri++) {
            float p = rowacc[ri];
            p += __shfl_xor_sync(0xffffffffu, p, 1);
            p += __shfl_xor_sync(0xffffffffu, p, 2);
            if ((lane & 3) == 0) {
                int row = mw * 32 + (ri >> 1) * 16 + (ri & 1) * 8 + (lane >> 2);
                red[(nw - 2) * 128 + row] = p;
            }
        }
    }
    __syncthreads();
    if (tid < BATCH)
        g_part[(size_t)task * BATCH + tid] = red[tid] + red[128 + tid];
}

// ---------------- softmax over instance axis (sums 4 l-chunk partials) ----------------
__global__ void softmax_kernel(float* __restrict__ out)
{
    const int b   = blockIdx.x;    // 0..127
    const int tid = threadIdx.x;   // 0..255 == n
    __shared__ float sh[256];

    const float* p = g_part + ((size_t)tid * 4) * BATCH + b;
    float s = p[0] + p[BATCH] + p[2 * BATCH] + p[3 * BATCH];
    sh[tid] = s;
    __syncthreads();
#pragma unroll
    for (int off = 128; off > 0; off >>= 1) {
        if (tid < off) sh[tid] = fmaxf(sh[tid], sh[tid + off]);
        __syncthreads();
    }
    float m = sh[0];
    __syncthreads();
    float e = __expf(s - m);
    sh[tid] = e;
    __syncthreads();
#pragma unroll
    for (int off = 128; off > 0; off >>= 1) {
        if (tid < off) sh[tid] += sh[tid + off];
        __syncthreads();
    }
    out[(size_t)tid * BATCH + b] = e / sh[0];
}

extern "C" void kernel_launch(void* const* d_in, const int* in_sizes, int n_in,
                              void* d_out, int out_size)
{
    const float* x = (const float*)d_in[0];
    const float* v = (const float*)d_in[1];
    const float* u = (const float*)d_in[2];
    const float* w = (const float*)d_in[3];
    float* out = (float*)d_out;

    cudaFuncSetAttribute(mil_gemm_kernel,
                         cudaFuncAttributeMaxDynamicSharedMemorySize, SM_TOTAL);

    prep_x_kernel<<<32768, 256>>>((const float4*)x);
    prep_vu_kernel<<<2048, 256>>>(v, u);
    mil_gemm_kernel<<<1024, 512, SM_TOTAL>>>(w);
    softmax_kernel<<<BATCH, 256>>>(out);
}